// round 7
// baseline (speedup 1.0000x reference)
#include <cuda_runtime.h>
#include <cuda_bf16.h>
#include <cstdint>

// Problem shapes
#define Nrows 16384
#define Hd    512
#define Gg    2
#define Vv    320
#define Dd    256
#define GVc   640

typedef unsigned long long u64;

// ---------------------------------------------------------------------------
// Device scratch
// ---------------------------------------------------------------------------
__device__ float g_logits[(size_t)Nrows * GVc];                 // 41.9 MB
__device__ __nv_bfloat16 g_A_hi[(size_t)Nrows * Hd];            // 16.8 MB
__device__ __nv_bfloat16 g_A_lo[(size_t)Nrows * Hd];            // 16.8 MB
__device__ __nv_bfloat16 g_Wt_hi[(size_t)GVc * Hd];             // 0.65 MB
__device__ __nv_bfloat16 g_Wt_lo[(size_t)GVc * Hd];
__device__ float g_acc[GVc];
__device__ u64   g_best[Nrows * Gg];                            // packed argmax

// ---------------------------------------------------------------------------
// Helpers (baseline ISA only)
// ---------------------------------------------------------------------------
__device__ __forceinline__ uint32_t smem_u32(const void* p) {
    uint32_t a;
    asm("{ .reg .u64 t; cvta.to.shared.u64 t, %1; cvt.u32.u64 %0, t; }" : "=r"(a) : "l"(p));
    return a;
}
#define CP_ASYNC16(dst, src) \
    asm volatile("cp.async.cg.shared.global [%0], [%1], 16;" :: "r"(dst), "l"(src) : "memory")
#define CP_COMMIT() asm volatile("cp.async.commit_group;" ::: "memory")
#define CP_WAIT2()  asm volatile("cp.async.wait_group 2;" ::: "memory")
#define CP_WAIT0()  asm volatile("cp.async.wait_group 0;" ::: "memory")

#define LDSM_X4(r0, r1, r2, r3, a) \
    asm volatile("ldmatrix.sync.aligned.m8n8.x4.shared.b16 {%0,%1,%2,%3}, [%4];" \
        : "=r"(r0), "=r"(r1), "=r"(r2), "=r"(r3) : "r"(a))

#define MMA_BF16(c, a, b) \
    asm volatile("mma.sync.aligned.m16n8k16.row.col.f32.bf16.bf16.f32 " \
        "{%0,%1,%2,%3}, {%4,%5,%6,%7}, {%8,%9}, {%0,%1,%2,%3};" \
        : "+f"((c)[0]), "+f"((c)[1]), "+f"((c)[2]), "+f"((c)[3]) \
        : "r"((a)[0]), "r"((a)[1]), "r"((a)[2]), "r"((a)[3]), "r"((b)[0]), "r"((b)[1]))

#define SW64(o) ((o) ^ (((o) >> 3) & 0x30))

// order-preserving float -> uint32
__device__ __forceinline__ uint32_t f2o(float x) {
    uint32_t u = __float_as_uint(x);
    return (u & 0x80000000u) ? ~u : (u | 0x80000000u);
}
__device__ __forceinline__ u64 shfl_xor_u64(u64 v, int off) {
    uint32_t hi = (uint32_t)(v >> 32), lo = (uint32_t)v;
    hi = __shfl_xor_sync(0xffffffffu, hi, off);
    lo = __shfl_xor_sync(0xffffffffu, lo, off);
    return ((u64)hi << 32) | lo;
}

// ---------------------------------------------------------------------------
// Prep kernels
// ---------------------------------------------------------------------------
__global__ __launch_bounds__(256) void prep_W(const float* __restrict__ W) {
    int idx = blockIdx.x * 256 + threadIdx.x;        // 0..327679
    if (idx < GVc) g_acc[idx] = 0.0f;
    if (idx < Nrows * Gg) g_best[idx] = 0ULL;
    float x = W[idx];
    int k = idx / GVc, n = idx % GVc;
    __nv_bfloat16 h = __float2bfloat16_rn(x);
    float r = x - __bfloat162float(h);
    g_Wt_hi[(size_t)n * Hd + k] = h;
    g_Wt_lo[(size_t)n * Hd + k] = __float2bfloat16_rn(r);
}

__global__ __launch_bounds__(256) void prep_A(const float* __restrict__ A) {
    size_t idx = (size_t)blockIdx.x * 256 + threadIdx.x;   // over float4's
    float4 v = reinterpret_cast<const float4*>(A)[idx];
    __nv_bfloat16 h0 = __float2bfloat16_rn(v.x), h1 = __float2bfloat16_rn(v.y);
    __nv_bfloat16 h2 = __float2bfloat16_rn(v.z), h3 = __float2bfloat16_rn(v.w);
    __nv_bfloat162 hi01; hi01.x = h0; hi01.y = h1;
    __nv_bfloat162 hi23; hi23.x = h2; hi23.y = h3;
    __nv_bfloat162 lo01, lo23;
    lo01.x = __float2bfloat16_rn(v.x - __bfloat162float(h0));
    lo01.y = __float2bfloat16_rn(v.y - __bfloat162float(h1));
    lo23.x = __float2bfloat16_rn(v.z - __bfloat162float(h2));
    lo23.y = __float2bfloat16_rn(v.w - __bfloat162float(h3));
    reinterpret_cast<__nv_bfloat162*>(g_A_hi)[idx * 2 + 0] = hi01;
    reinterpret_cast<__nv_bfloat162*>(g_A_hi)[idx * 2 + 1] = hi23;
    reinterpret_cast<__nv_bfloat162*>(g_A_lo)[idx * 2 + 0] = lo01;
    reinterpret_cast<__nv_bfloat162*>(g_A_lo)[idx * 2 + 1] = lo23;
}

// ---------------------------------------------------------------------------
// bf16x3 GEMM + fused gumbel-argmax epilogue
// 128x64 CTA tile, BK=32, 4-stage cp.async, SW64 swizzle, 2 CTAs/SM.
// ---------------------------------------------------------------------------
#define NSTAGE 4
#define NCHUNK 16
#define STAGE_BYTES 24576
#define AHI_OFF 0
#define ALO_OFF 8192
#define BHI_OFF 16384
#define BLO_OFF 20480
#define GEMM_SMEM (NSTAGE * STAGE_BYTES + 1024)

__global__ __launch_bounds__(256, 2) void gemm_bf16x3(
    const float* __restrict__ bias, const float* __restrict__ gmb)
{
    extern __shared__ char dsm[];
    const uint32_t raw = smem_u32(dsm);
    const uint32_t sb = (raw + 1023u) & ~1023u;

    const int tid = threadIdx.x;
    const int wid = tid >> 5, lane = tid & 31;
    const int rowBase = blockIdx.y * 128;
    const int colBase = blockIdx.x * 64;
    const int warpM = (wid & 3) * 32;        // 4 warps over M=128
    const int warpN = (wid >> 2) * 32;       // 2 warps over N=64

    const __nv_bfloat16* __restrict__ Ah = g_A_hi;
    const __nv_bfloat16* __restrict__ Al = g_A_lo;
    const __nv_bfloat16* __restrict__ Bh = g_Wt_hi;
    const __nv_bfloat16* __restrict__ Bl = g_Wt_lo;

    const int ra0 = tid >> 2,          ca = tid & 3;
    const int ra1 = (tid + 256) >> 2;
    const int rb  = tid >> 2;

    auto load_stage = [&](int ck) {
        const uint32_t so = sb + (ck & 3) * STAGE_BYTES;
        const int kt = ck * 32;
        const uint32_t offA0 = SW64((uint32_t)(ra0 * 64 + ca * 16));
        const uint32_t offA1 = SW64((uint32_t)(ra1 * 64 + ca * 16));
        const uint32_t offB  = SW64((uint32_t)(rb  * 64 + ca * 16));
        CP_ASYNC16(so + AHI_OFF + offA0, &Ah[(size_t)(rowBase + ra0) * Hd + kt + ca * 8]);
        CP_ASYNC16(so + AHI_OFF + offA1, &Ah[(size_t)(rowBase + ra1) * Hd + kt + ca * 8]);
        CP_ASYNC16(so + ALO_OFF + offA0, &Al[(size_t)(rowBase + ra0) * Hd + kt + ca * 8]);
        CP_ASYNC16(so + ALO_OFF + offA1, &Al[(size_t)(rowBase + ra1) * Hd + kt + ca * 8]);
        CP_ASYNC16(so + BHI_OFF + offB,  &Bh[(size_t)(colBase + rb) * Hd + kt + ca * 8]);
        CP_ASYNC16(so + BLO_OFF + offB,  &Bl[(size_t)(colBase + rb) * Hd + kt + ca * 8]);
    };

    float c[2][4][4];
    #pragma unroll
    for (int i = 0; i < 2; i++)
        #pragma unroll
        for (int j = 0; j < 4; j++)
            #pragma unroll
            for (int k = 0; k < 4; k++) c[i][j][k] = 0.0f;

    const uint32_t a_row = warpM + (lane & 15);
    const uint32_t a_colpart = (lane >> 4) * 16;
    const uint32_t b_row = warpN + ((lane >> 4) ? 8u : 0u) + (lane & 7);
    const uint32_t b_colpart = ((lane >> 3) & 1) * 16;
    uint32_t aoffK[2][2], boffK[2][2];
    #pragma unroll
    for (int p = 0; p < 2; p++)
        #pragma unroll
        for (int ma = 0; ma < 2; ma++) {
            aoffK[p][ma] = SW64((a_row + ma * 16) * 64 + p * 32 + a_colpart);
            boffK[p][ma] = SW64((b_row + ma * 16) * 64 + p * 32 + b_colpart);
        }

    uint32_t ah[2][2][4], bh[2][4][2];
    uint32_t al[2][4], bl[4][2];

    load_stage(0); CP_COMMIT();
    load_stage(1); CP_COMMIT();
    load_stage(2); CP_COMMIT();

    for (int ck = 0; ck < NCHUNK; ck++) {
        CP_WAIT2();
        __syncthreads();
        if (ck + 3 < NCHUNK) load_stage(ck + 3);
        CP_COMMIT();

        const uint32_t so  = sb + (ck & 3) * STAGE_BYTES;
        const uint32_t soN = sb + ((ck + 1) & 3) * STAGE_BYTES;

        if (ck == 0) {
            #pragma unroll
            for (int ma = 0; ma < 2; ma++)
                LDSM_X4(ah[0][ma][0], ah[0][ma][1], ah[0][ma][2], ah[0][ma][3],
                        so + AHI_OFF + aoffK[0][ma]);
            #pragma unroll
            for (int pp = 0; pp < 2; pp++) {
                uint32_t q0, q1, q2, q3;
                LDSM_X4(q0, q1, q2, q3, so + BHI_OFF + boffK[0][pp]);
                bh[0][2*pp][0] = q0; bh[0][2*pp][1] = q1;
                bh[0][2*pp+1][0] = q2; bh[0][2*pp+1][1] = q3;
            }
        }

        #pragma unroll
        for (int p = 0; p < 2; p++) {
            const int q = p ^ 1;
            const uint32_t soPF = (p == 0) ? so : soN;

            #pragma unroll
            for (int ma = 0; ma < 2; ma++)
                #pragma unroll
                for (int nb = 0; nb < 4; nb++) MMA_BF16(c[ma][nb], ah[p][ma], bh[p][nb]);

            #pragma unroll
            for (int ma = 0; ma < 2; ma++)
                LDSM_X4(al[ma][0], al[ma][1], al[ma][2], al[ma][3],
                        so + ALO_OFF + aoffK[p][ma]);
            #pragma unroll
            for (int pp = 0; pp < 2; pp++) {
                uint32_t q0, q1, q2, q3;
                LDSM_X4(q0, q1, q2, q3, so + BLO_OFF + boffK[p][pp]);
                bl[2*pp][0] = q0; bl[2*pp][1] = q1;
                bl[2*pp+1][0] = q2; bl[2*pp+1][1] = q3;
            }

            #pragma unroll
            for (int ma = 0; ma < 2; ma++)
                LDSM_X4(ah[q][ma][0], ah[q][ma][1], ah[q][ma][2], ah[q][ma][3],
                        soPF + AHI_OFF + aoffK[q][ma]);
            #pragma unroll
            for (int pp = 0; pp < 2; pp++) {
                uint32_t q0, q1, q2, q3;
                LDSM_X4(q0, q1, q2, q3, soPF + BHI_OFF + boffK[q][pp]);
                bh[q][2*pp][0] = q0; bh[q][2*pp][1] = q1;
                bh[q][2*pp+1][0] = q2; bh[q][2*pp+1][1] = q3;
            }

            #pragma unroll
            for (int ma = 0; ma < 2; ma++)
                #pragma unroll
                for (int nb = 0; nb < 4; nb++) MMA_BF16(c[ma][nb], al[ma], bh[p][nb]);

            #pragma unroll
            for (int ma = 0; ma < 2; ma++)
                #pragma unroll
                for (int nb = 0; nb < 4; nb++) MMA_BF16(c[ma][nb], ah[p][ma], bl[nb]);
        }
    }
    CP_WAIT0();
    __syncthreads();

    // ---- epilogue: bias + store logits + fused gumbel argmax ----
    u64* sArg = reinterpret_cast<u64*>(dsm);      // stage smem is dead; reuse
    if (tid < 128) sArg[tid] = 0ULL;
    __syncthreads();

    const int g = (colBase >= Vv) ? 1 : 0;
    const int vBase = colBase + warpN - g * Vv;   // within-group col of this warp

    float bv[8];
    #pragma unroll
    for (int nb = 0; nb < 4; nb++) {
        int cc = colBase + warpN + nb * 8 + (lane & 3) * 2;
        bv[2*nb]   = bias[cc];
        bv[2*nb+1] = bias[cc + 1];
    }

    #pragma unroll
    for (int ma = 0; ma < 2; ma++) {
        #pragma unroll
        for (int h = 0; h < 2; h++) {
            const int rloc = warpM + ma * 16 + h * 8 + (lane >> 2);
            const int r = rowBase + rloc;
            const float* grow = &gmb[(size_t)(2 * r + g) * Vv + vBase];
            float best = -1e30f; int bidx = 0;
            #pragma unroll
            for (int nb = 0; nb < 4; nb++) {
                const int lc = nb * 8 + (lane & 3) * 2;
                float l0 = c[ma][nb][2*h + 0] + bv[2*nb];
                float l1 = c[ma][nb][2*h + 1] + bv[2*nb + 1];
                *reinterpret_cast<float2*>(
                    &g_logits[(size_t)r * GVc + colBase + warpN + lc]) =
                    make_float2(l0, l1);
                float s0 = l0 + grow[lc];
                float s1 = l1 + grow[lc + 1];
                int v0 = vBase + lc;
                if (s0 > best) { best = s0; bidx = v0; }
                if (s1 > best) { best = s1; bidx = v0 + 1; }
            }
            u64 pack = ((u64)f2o(best) << 32) | (uint32_t)(~bidx);
            #pragma unroll
            for (int off = 1; off <= 2; off <<= 1) {
                u64 o = shfl_xor_u64(pack, off);
                if (o > pack) pack = o;
            }
            if ((lane & 3) == 0) atomicMax(&sArg[rloc], pack);
        }
    }
    __syncthreads();
    if (tid < 128) atomicMax(&g_best[(size_t)(rowBase + tid) * Gg + g], sArg[tid]);
}

// ---------------------------------------------------------------------------
// Rows: one warp per (n,g): masked softmax marginal + one-hot gather
// (argmax already computed by GEMM epilogue)
// ---------------------------------------------------------------------------
#define RPB 32

__global__ __launch_bounds__(256) void rows_kernel(
    const int*   __restrict__ mask,
    const float* __restrict__ codevectors,
    float*       __restrict__ out)
{
    __shared__ float sAcc[GVc];
    const int tid = threadIdx.x, lane = tid & 31, warp = tid >> 5;

    for (int i = tid; i < GVc; i += 256) sAcc[i] = 0.0f;
    __syncthreads();

    const int base = blockIdx.x * RPB;
    for (int rr = warp; rr < RPB; rr += 8) {
        const int row = base + rr;
        const int n = row >> 1, g = row & 1;
        const float* lrow = &g_logits[(size_t)n * GVc + g * Vv];

        float lv[10], ev[10];
        float mx = -1e30f;
        #pragma unroll
        for (int t = 0; t < 10; t++) {
            float x = lrow[lane + 32 * t];
            lv[t] = x;
            mx = fmaxf(mx, x);
        }
        #pragma unroll
        for (int off = 16; off; off >>= 1)
            mx = fmaxf(mx, __shfl_xor_sync(0xffffffffu, mx, off));
        float sum = 0.0f;
        #pragma unroll
        for (int t = 0; t < 10; t++) { ev[t] = __expf(lv[t] - mx); sum += ev[t]; }
        #pragma unroll
        for (int off = 16; off; off >>= 1) sum += __shfl_xor_sync(0xffffffffu, sum, off);
        const float inv = 1.0f / sum;

        if (mask[n] != 0) {
            #pragma unroll
            for (int t = 0; t < 10; t++)
                atomicAdd(&sAcc[g * Vv + lane + 32 * t], ev[t] * inv);
        }
        const int besti = (int)(uint32_t)(~(uint32_t)g_best[row]);
        const float4* src = reinterpret_cast<const float4*>(
            &codevectors[((size_t)g * Vv + besti) * (Dd / Gg)]);
        float4* dst = reinterpret_cast<float4*>(&out[(size_t)n * Dd + g * (Dd / Gg)]);
        dst[lane] = src[lane];
    }
    __syncthreads();
    for (int i = tid; i < GVc; i += 256) atomicAdd(&g_acc[i], sAcc[i]);
}

// ---------------------------------------------------------------------------
// Finalize: mask count + perplexity (640 threads, deterministic)
// ---------------------------------------------------------------------------
__global__ __launch_bounds__(640) void finalize_kernel(
    const int* __restrict__ mask, float* __restrict__ out, int out_size)
{
    __shared__ float  mred[640];
    __shared__ double wsum[20];
    const int tid = threadIdx.x, lane = tid & 31, warp = tid >> 5;

    float cnt = 0.0f;
    for (int i = tid; i < Nrows / 4; i += 640) {
        int4 m = reinterpret_cast<const int4*>(mask)[i];
        cnt += (m.x != 0) + (m.y != 0) + (m.z != 0) + (m.w != 0);
    }
    #pragma unroll
    for (int off = 16; off; off >>= 1) cnt += __shfl_xor_sync(0xffffffffu, cnt, off);
    if (lane == 0) mred[warp] = cnt;
    __syncthreads();
    double msum = 0.0;
    for (int w = 0; w < 20; w++) msum += (double)mred[w];

    double marg = (double)g_acc[tid] / msum;
    double t = marg * log(marg + 1e-7);
    #pragma unroll
    for (int off = 16; off; off >>= 1)
        t += __shfl_xor_sync(0xffffffffu, t, off);
    if (lane == 0) wsum[warp] = t;
    __syncthreads();
    if (tid == 0) {
        double e0 = 0.0, e1 = 0.0;
        for (int w = 0; w < 10; w++)  e0 += wsum[w];
        for (int w = 10; w < 20; w++) e1 += wsum[w];
        out[out_size - 1] = (float)(exp(-e0) + exp(-e1));
    }
}

// ---------------------------------------------------------------------------
extern "C" void kernel_launch(void* const* d_in, const int* in_sizes, int n_in,
                              void* d_out, int out_size)
{
    (void)in_sizes; (void)n_in;
    const float* hs   = (const float*)d_in[0];
    const int*   mask = (const int*)  d_in[1];
    const float* W    = (const float*)d_in[2];
    const float* bias = (const float*)d_in[3];
    const float* cb   = (const float*)d_in[4];
    const float* gmb  = (const float*)d_in[5];
    float* out = (float*)d_out;

    static bool attr_set = false;
    if (!attr_set) {
        cudaFuncSetAttribute(gemm_bf16x3, cudaFuncAttributeMaxDynamicSharedMemorySize, GEMM_SMEM);
        attr_set = true;
    }

    prep_W<<<(Hd * GVc) / 256, 256>>>(W);
    prep_A<<<(Nrows * Hd / 4) / 256, 256>>>(hs);

    dim3 ggrid(GVc / 64, Nrows / 128);   // (10, 128) = 1280 CTAs
    gemm_bf16x3<<<ggrid, 256, GEMM_SMEM>>>(bias, gmb);

    rows_kernel<<<(Nrows * Gg) / RPB, 256>>>(mask, cb, out);
    finalize_kernel<<<1, 640>>>(mask, out, out_size);
}